// round 16
// baseline (speedup 1.0000x reference)
#include <cuda_runtime.h>
#include <cuda_bf16.h>
#include <cuda_fp16.h>
#include <math.h>
#include <stdint.h>

// ---------------------------------------------------------------------------
// SelfAttentionConv: B=8, T=1024, K=128, H=8, TOP_K=64, KS=5
// Round 16: R15 build (970.8us) with k_s_mma retiled 128x64 -> 128x128
// (512 thr, 16 warps, 136KB smem): per-CTA tile fills drop 32% in L2 traffic.
// Arithmetic identical.
// ---------------------------------------------------------------------------

#define SCALE_QK 0.2973017787506803f   // 128^-0.25

__device__ float g_S    [67108864];        // 64 * 1024 * 1024 fp32 scores
__device__ float g_O    [8388608];         // 64 * 1024 * 128
__device__ float g_stats[65536 * 4];       // per-row: thresh, rmin, off, pad
__device__ float g_WuT  [1024 * 128];
// fp16 hi/lo operand planes
__device__ __align__(128) __half g_xh  [1052672];   // [b][1028][128], 4 pad rows
__device__ __align__(128) __half g_xl  [1052672];
__device__ __align__(128) __half g_WqTh[655360];    // [cg][640] K-major
__device__ __align__(128) __half g_WqTl[655360];
__device__ __align__(128) __half g_WkTh[655360];
__device__ __align__(128) __half g_WkTl[655360];
__device__ __align__(128) __half g_WvTh[131072];    // [cg][128]
__device__ __align__(128) __half g_WvTl[131072];
__device__ __align__(128) __half g_Qh[8388608];     // [g][ki] fp16 hi
__device__ __align__(128) __half g_Ql[8388608];
__device__ __align__(128) __half g_Kh[8388608];
__device__ __align__(128) __half g_Kl[8388608];
__device__ __align__(128) __half g_Vth[8388608];    // [bh][ki][s] fp16 hi
__device__ __align__(128) __half g_Vtl[8388608];    // fp16 lo

// ======================= mma.sync helpers ====================================
__device__ __forceinline__ uint32_t smem_u32(const void* p) {
    uint32_t a;
    asm("{ .reg .u64 t; cvta.to.shared.u64 t, %1; cvt.u32.u64 %0, t; }"
        : "=r"(a) : "l"(p));
    return a;
}
__device__ __forceinline__ void cpa16(uint32_t dst, const void* src) {
    asm volatile("cp.async.cg.shared.global [%0], [%1], 16;"
                 :: "r"(dst), "l"(src));
}
#define CPA_COMMIT() asm volatile("cp.async.commit_group;" ::: "memory")
#define CPA_WAIT(n)  asm volatile("cp.async.wait_group %0;" :: "n"(n) : "memory")

#define LDSM4(R, addr)                                                        \
    asm volatile("ldmatrix.sync.aligned.m8n8.x4.shared.b16 "                  \
                 "{%0, %1, %2, %3}, [%4];"                                    \
                 : "=r"((R)[0]), "=r"((R)[1]), "=r"((R)[2]), "=r"((R)[3])     \
                 : "r"(addr))

__device__ __forceinline__ void mma_f16(float* d, const unsigned* a,
                                        const unsigned* b) {
    asm volatile(
        "mma.sync.aligned.m16n8k16.row.col.f32.f16.f16.f32 "
        "{%0, %1, %2, %3}, {%4, %5, %6, %7}, {%8, %9}, {%0, %1, %2, %3};"
        : "+f"(d[0]), "+f"(d[1]), "+f"(d[2]), "+f"(d[3])
        : "r"(a[0]), "r"(a[1]), "r"(a[2]), "r"(a[3]), "r"(b[0]), "r"(b[1]));
}

// ---- k_s_mma smem layout (128x128 tile) --------------------------------------
#define SQ_AH 0
#define SQ_AL 34816
#define SQ_BH 69632
#define SQ_BL 104448
#define SMEM_S_BYTES 139264

// ---- conv smem ----------------------------------------------------------------
#define CV_AH 0
#define CV_AL 35904
#define CV_B  71808
#define SMEM_CONV_BYTES 211072

// ---- k_av smem: P fp16 plane + V fp16 hi/lo + fp32 S stage + stats ----------
#define TSTRIDE 272
#define S_AH  0
#define S_BH  34816
#define S_BL  69632
#define S_STG 104448
#define S_ST  169984
#define SMEM_AV_BYTES 172032

// ======================= FFMA2 helpers (proj only) ===========================
__device__ __forceinline__ unsigned long long fma2(unsigned long long a,
                                                   unsigned long long b,
                                                   unsigned long long c) {
    unsigned long long d;
    asm("fma.rn.f32x2 %0, %1, %2, %3;" : "=l"(d) : "l"(a), "l"(b), "l"(c));
    return d;
}
__device__ __forceinline__ float2 up2(unsigned long long v) {
    float2 r;
    asm("mov.b64 {%0, %1}, %2;" : "=f"(r.x), "=f"(r.y) : "l"(v));
    return r;
}
__device__ __forceinline__ unsigned long long dup2(float a) {
    unsigned long long d;
    asm("mov.b64 %0, {%1, %1};" : "=l"(d) : "f"(a));
    return d;
}
__device__ __forceinline__ void mm_step(const float* __restrict__ As,
                                        const float* __restrict__ Bs,
                                        int ty, int tx,
                                        unsigned long long acc[8][4]) {
#pragma unroll
    for (int kk = 0; kk < 8; kk++) {
        const float* ar = As + kk * 128;
        const float* br = Bs + kk * 128;
        float4 x0 = *(const float4*)(ar + ty * 4);
        float4 x1 = *(const float4*)(ar + 64 + ty * 4);
        ulonglong2 b01 = *(const ulonglong2*)(br + tx * 4);
        ulonglong2 b23 = *(const ulonglong2*)(br + 64 + tx * 4);
        unsigned long long a[8] = {dup2(x0.x), dup2(x0.y), dup2(x0.z), dup2(x0.w),
                                   dup2(x1.x), dup2(x1.y), dup2(x1.z), dup2(x1.w)};
        unsigned long long b[4] = {b01.x, b01.y, b23.x, b23.y};
#pragma unroll
        for (int i = 0; i < 8; i++)
#pragma unroll
            for (int p = 0; p < 4; p++)
                acc[i][p] = fma2(a[i], b[p], acc[i][p]);
    }
}
__device__ __forceinline__ int rowidx(int ty, int i) {
    return (i < 4) ? (ty * 4 + i) : (64 + ty * 4 + i - 4);
}
__device__ __forceinline__ float4 packrow(unsigned long long p0,
                                          unsigned long long p1) {
    float2 a = up2(p0), b = up2(p1);
    return make_float4(a.x, a.y, b.x, b.y);
}

// order-preserving float<->key bijection
__device__ __forceinline__ unsigned f2k(unsigned u) {
    return (u & 0x80000000u) ? ~u : (u | 0x80000000u);
}
__device__ __forceinline__ float k2f(unsigned k) {
    unsigned u = (k & 0x80000000u) ? (k & 0x7FFFFFFFu) : ~k;
    return __uint_as_float(u);
}

// ---------------- merged prep: pad/split x, split weights --------------------
#define PX_X  1052672
#define PX_WQ 1708032
#define PX_WK 2363392
#define PX_WV 2494464
#define PX_WU 2625536
__global__ void k_prep(const float* __restrict__ x,
                       const float* __restrict__ Wq, const float* __restrict__ Wk,
                       const float* __restrict__ Wv, const float* __restrict__ Wu) {
    int idx = blockIdx.x * 256 + threadIdx.x;
    if (idx < PX_X) {
        int b = idx / 131584, rem = idx % 131584;
        int row = rem >> 7, ci = rem & 127;
        int t = row - 4;
        float v = (t >= 0) ? x[(((b << 10) | t) << 7) + ci] : 0.f;
        __half h = __float2half_rn(v);
        g_xh[idx] = h;
        g_xl[idx] = __float2half_rn(v - __half2float(h));
    } else if (idx < PX_WQ) {
        int i = idx - PX_X;
        int cg = i / 640, k = i % 640, j = k >> 7, ci = k & 127;
        float v = Wq[(cg * 128 + ci) * 5 + j];
        __half h = __float2half_rn(v);
        g_WqTh[i] = h;
        g_WqTl[i] = __float2half_rn(v - __half2float(h));
    } else if (idx < PX_WK) {
        int i = idx - PX_WQ;
        int cg = i / 640, k = i % 640, j = k >> 7, ci = k & 127;
        float v = Wk[(cg * 128 + ci) * 5 + j];
        __half h = __float2half_rn(v);
        g_WkTh[i] = h;
        g_WkTl[i] = __float2half_rn(v - __half2float(h));
    } else if (idx < PX_WV) {
        int i = idx - PX_WK;
        float v = Wv[i];
        __half h = __float2half_rn(v);
        g_WvTh[i] = h;
        g_WvTl[i] = __float2half_rn(v - __half2float(h));
    } else if (idx < PX_WU) {
        int i = idx - PX_WV;
        int c = i >> 7, n = i & 127;
        g_WuT[i] = Wu[n * 1024 + c];
    }
}

// ---------------- pipelined conv via fp16x3 HMMA -----------------------------
__global__ __launch_bounds__(512, 1) void k_conv_mma(
    const float* __restrict__ bq, const float* __restrict__ bk,
    const float* __restrict__ bv)
{
    extern __shared__ char sm[];
    const uint32_t smb = smem_u32(sm);
    const int tid = threadIdx.x, lane = tid & 31, wid = tid >> 5;
    const int rowBase = blockIdx.y * 128;
    const int colBase = blockIdx.x * 128;
    const int z = blockIdx.z;
    const int b = rowBase >> 10, t0 = rowBase & 1023;
    const int wm = wid >> 2, wn = wid & 3;

    const __half* Wth = (z == 0) ? g_WqTh : (z == 1) ? g_WkTh : g_WvTh;
    const __half* Wtl = (z == 0) ? g_WqTl : (z == 1) ? g_WkTl : g_WvTl;
    const float* bias = (z == 0) ? bq : (z == 1) ? bk : bv;
    const float scale = (z == 2) ? 1.0f : SCALE_QK;
    const int nJ   = (z == 2) ? 1 : 5;
    const int tAdd = (z == 2) ? 4 : 0;
    const int Wstride = nJ * 128;

    {
        const size_t base = (size_t)(b * 1028 + t0) * 128;
#pragma unroll
        for (int i = 0; i < 5; i++) {
            int c = i * 512 + tid;
            if (c < 132 * 16) {
                int r = c >> 4, q = c & 15;
                uint32_t d = smb + CV_AH + r * 272 + q * 16;
                cpa16(d,         g_xh + base + (size_t)r * 128 + q * 8);
                cpa16(d + 35904, g_xl + base + (size_t)r * 128 + q * 8);
            }
        }
    }
#pragma unroll
    for (int i = 0; i < 4; i++) {
        int c = i * 512 + tid;
        int r = c >> 4, q = c & 15;
        uint32_t d = smb + CV_B + r * 272 + q * 16;
        size_t so = (size_t)(colBase + r) * Wstride + q * 8;
        cpa16(d,         Wth + so);
        cpa16(d + 34816, Wtl + so);
    }
    CPA_COMMIT();

    float acc[2][4][4];
#pragma unroll
    for (int i = 0; i < 2; i++)
#pragma unroll
        for (int j = 0; j < 4; j++)
#pragma unroll
            for (int e = 0; e < 4; e++) acc[i][j][e] = 0.f;

    const int aRow = wm * 32 + (lane & 7) + ((lane >> 3) & 1) * 8;
    const int aKb  = (lane >> 4) * 16;
    const int bRow = wn * 32 + ((lane >> 4) & 1) * 8 + (lane & 7);
    const int bKb  = ((lane >> 3) & 1) * 16;

    int buf = 0;
    for (int j = 0; j < nJ; j++) {
        CPA_WAIT(0);
        __syncthreads();

        if (j + 1 < nJ) {
#pragma unroll
            for (int i = 0; i < 4; i++) {
                int c = i * 512 + tid;
                int r = c >> 4, q = c & 15;
                uint32_t d = smb + CV_B + (buf ^ 1) * 69632 + r * 272 + q * 16;
                size_t so = (size_t)(colBase + r) * Wstride + (j + 1) * 128 + q * 8;
                cpa16(d,         Wth + so);
                cpa16(d + 34816, Wtl + so);
            }
            CPA_COMMIT();
        }

        const uint32_t aHj = smb + CV_AH + (aRow + j + tAdd) * 272 + aKb;
        const uint32_t aLj = aHj + 35904;
        const uint32_t bHj = smb + CV_B + buf * 69632 + bRow * 272 + bKb;
        const uint32_t bLj = bHj + 34816;

#pragma unroll
        for (int k = 0; k < 8; k++) {
            const int kb = k * 32;
            unsigned ah[2][4], al[2][4], bhr[4][2], blr[4][2];
#pragma unroll
            for (int mf = 0; mf < 2; mf++) {
                LDSM4(ah[mf], aHj + mf * 16 * 272 + kb);
                LDSM4(al[mf], aLj + mf * 16 * 272 + kb);
            }
#pragma unroll
            for (int g2 = 0; g2 < 2; g2++) {
                LDSM4(&bhr[2 * g2][0], bHj + g2 * 16 * 272 + kb);
                LDSM4(&blr[2 * g2][0], bLj + g2 * 16 * 272 + kb);
            }
#pragma unroll
            for (int mf = 0; mf < 2; mf++)
#pragma unroll
                for (int nf = 0; nf < 4; nf++) {
                    mma_f16(acc[mf][nf], ah[mf], bhr[nf]);
                    mma_f16(acc[mf][nf], ah[mf], blr[nf]);
                    mma_f16(acc[mf][nf], al[mf], bhr[nf]);
                }
        }
        buf ^= 1;
    }

    const int r0 = rowBase + wm * 32 + (lane >> 2);
    const int c0 = colBase + wn * 32 + (lane & 3) * 2;
#pragma unroll
    for (int mf = 0; mf < 2; mf++)
#pragma unroll
        for (int nf = 0; nf < 4; nf++)
#pragma unroll
            for (int e = 0; e < 4; e++) {
                int m  = r0 + mf * 16 + (e >> 1) * 8;
                int cg = c0 + nf * 8 + (e & 1);
                float val = (acc[mf][nf][e] + bias[cg]) * scale;
                int b2 = m >> 10, t2 = m & 1023;
                int hh = cg & 7, ki = cg >> 3;
                int g = (b2 << 13) | (t2 << 3) | hh;
                __half h = __float2half_rn(val);
                __half l = __float2half_rn(val - __half2float(h));
                if (z == 0) {
                    g_Qh[(size_t)g * 128 + ki] = h;
                    g_Ql[(size_t)g * 128 + ki] = l;
                } else if (z == 1) {
                    g_Kh[(size_t)g * 128 + ki] = h;
                    g_Kl[(size_t)g * 128 + ki] = l;
                } else {
                    size_t idx = (size_t)((g >> 10) * 128 + ki) * 1024 + (g & 1023);
                    g_Vth[idx] = h;
                    g_Vtl[idx] = l;
                }
            }
}

// ---------------- S = Q K^T via mma.sync fp16x3, 128x128 tiles ---------------
__global__ __launch_bounds__(512, 1) void k_s_mma() {
    extern __shared__ char sm[];
    const uint32_t smb = smem_u32(sm);
    const int tid = threadIdx.x, lane = tid & 31, wid = tid >> 5;
    const int nt = blockIdx.x, mt = blockIdx.y, bh = blockIdx.z;
    const int wm = wid >> 2, wn = wid & 3;

    const __half* Ah = g_Qh + ((size_t)((bh << 10) + mt * 128)) * 128;
    const __half* Al = g_Ql + ((size_t)((bh << 10) + mt * 128)) * 128;
    const __half* Bh = g_Kh + ((size_t)((bh << 10) + nt * 128)) * 128;
    const __half* Bl = g_Kl + ((size_t)((bh << 10) + nt * 128)) * 128;

    // 4 planes, each 128 rows x 256 B
#pragma unroll
    for (int i = 0; i < 4; i++) {
        int c = i * 512 + tid;
        int r = c >> 4, j = c & 15;
        uint32_t d = smb + r * 272 + j * 16;
        const size_t so = (size_t)r * 128 + j * 8;
        cpa16(d + SQ_AH, Ah + so);
        cpa16(d + SQ_AL, Al + so);
        cpa16(d + SQ_BH, Bh + so);
        cpa16(d + SQ_BL, Bl + so);
    }
    CPA_COMMIT();
    CPA_WAIT(0);
    __syncthreads();

    float acc[2][4][4];
#pragma unroll
    for (int i = 0; i < 2; i++)
#pragma unroll
        for (int j = 0; j < 4; j++)
#pragma unroll
            for (int e = 0; e < 4; e++) acc[i][j][e] = 0.f;

    const int aRow = wm * 32 + (lane & 7) + ((lane >> 3) & 1) * 8;
    const int aKb  = (lane >> 4) * 16;
    const int bRow = wn * 32 + ((lane >> 4) & 1) * 8 + (lane & 7);
    const int bKb  = ((lane >> 3) & 1) * 16;
    const uint32_t aH = smb + SQ_AH + aRow * 272 + aKb;
    const uint32_t aL = smb + SQ_AL + aRow * 272 + aKb;
    const uint32_t bH = smb + SQ_BH + bRow * 272 + bKb;
    const uint32_t bL = smb + SQ_BL + bRow * 272 + bKb;

#pragma unroll
    for (int k = 0; k < 8; k++) {
        const int kb = k * 32;
        unsigned ah[2][4], al[2][4], bhr[4][2], blr[4][2];
#pragma unroll
        for (int mf = 0; mf < 2; mf++) {
            LDSM4(ah[mf], aH + mf * 16 * 272 + kb);
            LDSM4(al[mf], aL + mf * 16 * 272 + kb);
        }
#pragma unroll
        for (int g2 = 0; g2 < 2; g2++) {
            LDSM4(&bhr[2 * g2][0], bH + g2 * 16 * 272 + kb);
            LDSM4(&blr[2 * g2][0], bL + g2 * 16 * 272 + kb);
        }
#pragma unroll
        for (int mf = 0; mf < 2; mf++)
#pragma unroll
            for (int nf = 0; nf < 4; nf++) {
                mma_f16(acc[mf][nf], ah[mf], bhr[nf]);
                mma_f16(acc[mf][nf], ah[mf], blr[nf]);
                mma_f16(acc[mf][nf], al[mf], bhr[nf]);
            }
    }

    float* C = g_S + ((size_t)bh << 20);
    const int r0 = mt * 128 + wm * 32 + (lane >> 2);
    const int c0 = nt * 128 + wn * 32 + (lane & 3) * 2;
#pragma unroll
    for (int mf = 0; mf < 2; mf++)
#pragma unroll
        for (int nf = 0; nf < 4; nf++) {
            int rr = r0 + mf * 16, cc = c0 + nf * 8;
            *(float2*)&C[(size_t)rr * 1024 + cc] =
                make_float2(acc[mf][nf][0], acc[mf][nf][1]);
            *(float2*)&C[(size_t)(rr + 8) * 1024 + cc] =
                make_float2(acc[mf][nf][2], acc[mf][nf][3]);
        }
}

// ---------------- per-row stats: R14 radix, key-resident registers -----------
__global__ __launch_bounds__(256) void k_stats() {
    __shared__ unsigned hist[8][256];
    const int tid = threadIdx.x, lane = tid & 31, wid = tid >> 5;
    const int t  = blockIdx.x * 8 + wid;
    const int bh = blockIdx.y;
    const float* row = g_S + ((size_t)bh << 20) + ((size_t)t << 10);

    unsigned keys[32];
#pragma unroll
    for (int i = 0; i < 8; i++) {
        uint4 v = ((const uint4*)row)[lane + i * 32];
        keys[i * 4 + 0] = f2k(v.x);
        keys[i * 4 + 1] = f2k(v.y);
        keys[i * 4 + 2] = f2k(v.z);
        keys[i * 4 + 3] = f2k(v.w);
    }

    unsigned kmin = keys[0];
#pragma unroll
    for (int i = 1; i < 32; i++) kmin = min(kmin, keys[i]);
#pragma unroll
    for (int off = 16; off; off >>= 1)
        kmin = min(kmin, __shfl_xor_sync(0xffffffffu, kmin, off));

    unsigned prefix = 0u, need = 64u;
#pragma unroll
    for (int pass = 0; pass < 4; pass++) {
        const int shift = 24 - pass * 8;
        const unsigned mask = (pass == 0) ? 0u : (0xFFFFFFFFu << (shift + 8));
#pragma unroll
        for (int j = 0; j < 8; j++) hist[wid][lane * 8 + j] = 0u;
        __syncwarp();
#pragma unroll
        for (int i = 0; i < 32; i++) {
            if ((keys[i] & mask) == prefix)
                atomicAdd(&hist[wid][(keys[i] >> shift) & 255u], 1u);
        }
        __syncwarp();
        unsigned h8[8], suf[8], run = 0u;
#pragma unroll
        for (int j = 7; j >= 0; j--) {
            h8[j] = hist[wid][lane * 8 + j];
            run += h8[j];
            suf[j] = run;
        }
        unsigned s = run;
#pragma unroll
        for (int off = 1; off < 32; off <<= 1) {
            unsigned v = __shfl_down_sync(0xffffffffu, s, off);
            if (lane + off < 32) s += v;
        }
        unsigned tail = s - run;
        int sel = -1; unsigned nneed = 0u;
#pragma unroll
        for (int j = 0; j < 8; j++) {
            unsigned cum  = suf[j] + tail;
            unsigned cumN = cum - h8[j];
            if (cum >= need && cumN < need) { sel = lane * 8 + j; nneed = need - cumN; }
        }
        unsigned bal = __ballot_sync(0xffffffffu, sel >= 0);
        int src = __ffs(bal) - 1;
        sel   = __shfl_sync(0xffffffffu, sel, src);
        nneed = __shfl_sync(0xffffffffu, nneed, src);
        prefix |= ((unsigned)sel << shift);
        need = nneed;
        __syncwarp();
    }
    const unsigned tkey = prefix;
    const float thresh = k2f(tkey);

    float mx = -1e30f;
    float fv[32];
#pragma unroll
    for (int i = 0; i < 32; i++) {
        int s_ = 4 * (lane + (i >> 2) * 32) + (i & 3);
        unsigned pk = (keys[i] >= tkey) ? keys[i] : kmin;
        float pv = k2f(pk);
        fv[i] = pv;
        if (s_ <= t) mx = fmaxf(mx, pv);
    }
#pragma unroll
    for (int off = 16; off; off >>= 1)
        mx = fmaxf(mx, __shfl_xor_sync(0xffffffffu, mx, off));
    float lsum = 0.f;
#pragma unroll
    for (int i = 0; i < 32; i++) {
        int s_ = 4 * (lane + (i >> 2) * 32) + (i & 3);
        if (s_ <= t) lsum += __expf(fv[i] - mx);
    }
#pragma unroll
    for (int off = 16; off; off >>= 1)
        lsum += __shfl_xor_sync(0xffffffffu, lsum, off);
    if (lane == 0) {
        float off0 = mx + __logf(lsum);
        ((float4*)g_stats)[(bh << 10) + t] =
            make_float4(thresh, k2f(kmin), off0, 0.f);
    }
}

// ---------------- O = P V via mma.sync fp16x2 (staged causal pipeline) -------
__global__ __launch_bounds__(512, 1) void k_av_mma() {
    extern __shared__ char sm[];
    const int tid = threadIdx.x, lane = tid & 31, wid = tid >> 5;
    const int mt = gridDim.x - 1 - blockIdx.x;   // longest CTAs first
    const int bh = blockIdx.y;
    const int rowBase = mt * 128;
    const uint32_t smb = smem_u32(sm);
    const int wm = wid >> 2, wn = wid & 3;

    if (tid < 128)
        ((float4*)(sm + S_ST))[tid] =
            ((const float4*)g_stats)[(bh << 10) + rowBase + tid];

#pragma unroll
    for (int it = 0; it < 8; it++) {
        int idx = it * 512 + tid;
        int r = idx >> 5, j = idx & 31;
        cpa16(smb + S_STG + r * 512 + j * 16,
              &g_S[((size_t)bh << 20) + (size_t)(rowBase + r) * 1024 + j * 4]);
    }
    CPA_COMMIT();

    float acc[2][4][4];
#pragma unroll
    for (int i = 0; i < 2; i++)
#pragma unroll
        for (int j = 0; j < 4; j++)
#pragma unroll
            for (int e = 0; e < 4; e++) acc[i][j][e] = 0.f;

    const int aRow = wm * 32 + (lane & 7) + ((lane >> 3) & 1) * 8;
    const int aKb  = (lane >> 4) * 16;
    const int bRow = wn * 32 + ((lane >> 4) & 1) * 8 + (lane & 7);
    const int bKb  = ((lane >> 3) & 1) * 16;
    const uint32_t pH = smb + S_AH + aRow * TSTRIDE + aKb;
    const uint32_t vH = smb + S_BH + bRow * TSTRIDE + bKb;
    const uint32_t vL = smb + S_BL + bRow * TSTRIDE + bKb;

    const int nChunks = mt + 1;
    for (int c = 0; c < nChunks; c++) {
        const int kt = c * 128;
        CPA_WAIT(0);
        __syncthreads();

#pragma unroll
        for (int it = 0; it < 4; it++) {
            int idx = it * 512 + tid;
            int r = idx >> 4, j = idx & 15;
            uint32_t d = smb + S_BH + r * TSTRIDE + j * 16;
            cpa16(d, (const char*)(g_Vth + (size_t)(bh * 128 + r) * 1024 + kt) + j * 16);
            cpa16(d + 34816,
                  (const char*)(g_Vtl + (size_t)(bh * 128 + r) * 1024 + kt) + j * 16);
        }
        CPA_COMMIT();

        // transform staged S chunk -> P (threshold + causal + exp) fp16 plane
#pragma unroll
        for (int i = 0; i < 8; i++) {
            int idx4 = i * 512 + tid;
            int r = idx4 >> 5;
            int s4 = (idx4 & 31) * 4;
            float4 st = ((const float4*)(sm + S_ST))[r];
            const float th = st.x, rm = st.y, off0 = st.z;
            const int tg = rowBase + r;
            float4 v = *(const float4*)(sm + S_STG + r * 512 + s4 * 4);
            float pv[4] = { v.x, v.y, v.z, v.w };
            __half hb[4];
#pragma unroll
            for (int j = 0; j < 4; j++) {
                int sg = kt + s4 + j;
                float p = (pv[j] >= th) ? pv[j] : rm;
                p = (sg <= tg) ? __expf(p - off0) : 0.f;
                hb[j] = __float2half_rn(p);
            }
            __half2 h01 = __halves2half2(hb[0], hb[1]);
            __half2 h23 = __halves2half2(hb[2], hb[3]);
            int off = r * TSTRIDE + s4 * 2;
            *(uint2*)(sm + S_AH + off) =
                make_uint2(*(unsigned*)&h01, *(unsigned*)&h23);
        }
        __syncthreads();

        if (c + 1 < nChunks) {
            const int kt2 = kt + 128;
#pragma unroll
            for (int it = 0; it < 8; it++) {
                int idx = it * 512 + tid;
                int r = idx >> 5, j = idx & 31;
                cpa16(smb + S_STG + r * 512 + j * 16,
                      &g_S[((size_t)bh << 20) + (size_t)(rowBase + r) * 1024
                           + kt2 + j * 4]);
            }
            CPA_COMMIT();
            CPA_WAIT(1);
        } else {
            CPA_WAIT(0);
        }
        __syncthreads();

#pragma unroll
        for (int k = 0; k < 8; k++) {
            const int kb = k * 32;
            unsigned ah[2][4], bhr[4][2], blr[4][2];
#pragma unroll
            for (int mf = 0; mf < 2; mf++)
                LDSM4(ah[mf], pH + mf * 16 * TSTRIDE + kb);
#pragma unroll
            for (int g2 = 0; g2 < 2; g2++) {
                LDSM4(&bhr[2 * g2][0], vH + g2 * 16 * TSTRIDE + kb);
                LDSM4(&blr[2 * g2][0], vL + g2 * 16 * TSTRIDE + kb);
            }
#pragma unroll
            for (int mf = 0; mf < 2; mf++)
#pragma unroll
                for (int nf = 0; nf < 4; nf++) {
                    mma_f16(acc[mf][nf], ah[mf], bhr[nf]);
                    mma_f16(acc[mf][nf], ah[mf], blr[nf]);
                }
        }
    }

    const int r0 = (bh << 10) + rowBase + wm * 32 + (lane >> 2);
    const int c0 = wn * 32 + (lane & 3) * 2;
#pragma unroll
    for (int mf = 0; mf < 2; mf++)
#pragma unroll
        for (int nf = 0; nf < 4; nf++) {
            int rr = r0 + mf * 16, cc = c0 + nf * 8;
            *(float2*)&g_O[(size_t)rr * 128 + cc] =
                make_float2(acc[mf][nf][0], acc[mf][nf][1]);
            *(float2*)&g_O[(size_t)(rr + 8) * 128 + cc] =
                make_float2(acc[mf][nf][2], acc[mf][nf][3]);
        }
}

// ---------------- final projection (FFMA2) -----------------------------------
__global__ __launch_bounds__(256, 2) void k_proj(const float* __restrict__ bu,
                                                 float* __restrict__ out) {
    __shared__ __align__(16) float As [2][8][128];
    __shared__ __align__(16) float Bsm[2][8][128];
    unsigned long long acc[8][4];
#pragma unroll
    for (int i = 0; i < 8; i++)
#pragma unroll
        for (int p = 0; p < 4; p++) acc[i][p] = 0ull;

    const int tid = threadIdx.x;
    const int ty = tid >> 4, tx = tid & 15;
    const int rowBase = blockIdx.x * 128;
    const int lm = tid >> 1, lk4 = (tid & 1) * 4;
    const int bk = tid >> 5, bn4 = (tid & 31) * 4;
    const int m = rowBase + lm;
    const int b = m >> 10, tf = m & 1023;

    float4 av, bv;
    {
        int hf = lk4 >> 7, ki = lk4 & 127;
        av = *(const float4*)&g_O[(size_t)(((b << 13) + (hf << 10) + tf) << 7) + ki];
        bv = *(const float4*)&g_WuT[bk * 128 + bn4];
    }
    As[0][lk4 + 0][lm] = av.x; As[0][lk4 + 1][lm] = av.y;
    As[0][lk4 + 2][lm] = av.z; As[0][lk4 + 3][lm] = av.w;
    *(float4*)&Bsm[0][bk][bn4] = bv;
    __syncthreads();

    int buf = 0;
    for (int kt = 8; kt < 1024; kt += 8) {
        int k4 = kt + lk4;
        int hf = k4 >> 7, ki = k4 & 127;
        av = *(const float4*)&g_O[(size_t)(((b << 13) + (hf << 10) + tf) << 7) + ki];
        bv = *(const float4*)&g_WuT[(kt + bk) * 128 + bn4];
        mm_step(&As[buf][0][0], &Bsm[buf][0][0], ty, tx, acc);
        buf ^= 1;
        As[buf][lk4 + 0][lm] = av.x; As[buf][lk4 + 1][lm] = av.y;
        As[buf][lk4 + 2][lm] = av.z; As[buf][lk4 + 3][lm] = av.w;
        *(float4*)&Bsm[buf][bk][bn4] = bv;
        __syncthreads();
    }
    mm_step(&As[buf][0][0], &Bsm[buf][0][0], ty, tx, acc);

#pragma unroll
    for (int i = 0; i < 8; i++) {
        int rr = rowidx(ty, i);
        float4 lo = packrow(acc[i][0], acc[i][1]);
        float4 hi = packrow(acc[i][2], acc[i][3]);
        int c0 = tx * 4;
        lo.x += bu[c0];      lo.y += bu[c0 + 1];
        lo.z += bu[c0 + 2];  lo.w += bu[c0 + 3];
        hi.x += bu[64 + c0];     hi.y += bu[64 + c0 + 1];
        hi.z += bu[64 + c0 + 2]; hi.w += bu[64 + c0 + 3];
        *(float4*)&out[(rowBase + rr) * 128 + c0]      = lo;
        *(float4*)&out[(rowBase + rr) * 128 + 64 + c0] = hi;
    }
}

// ---------------------------------------------------------------------------
extern "C" void kernel_launch(void* const* d_in, const int* in_sizes, int n_in,
                              void* d_out, int out_size) {
    const float* x  = (const float*)d_in[0];
    const float* Wq = (const float*)d_in[1];
    const float* bq = (const float*)d_in[2];
    const float* Wk = (const float*)d_in[3];
    const float* bk = (const float*)d_in[4];
    const float* Wv = (const float*)d_in[5];
    const float* bv = (const float*)d_in[6];
    const float* Wu = (const float*)d_in[7];
    const float* bu = (const float*)d_in[8];
    float* out = (float*)d_out;

    cudaFuncSetAttribute(k_conv_mma,
        cudaFuncAttributeMaxDynamicSharedMemorySize, SMEM_CONV_BYTES);
    cudaFuncSetAttribute(k_s_mma,
        cudaFuncAttributeMaxDynamicSharedMemorySize, SMEM_S_BYTES);
    cudaFuncSetAttribute(k_av_mma,
        cudaFuncAttributeMaxDynamicSharedMemorySize, SMEM_AV_BYTES);

    k_prep<<<10256, 256>>>(x, Wq, Wk, Wv, Wu);

    k_conv_mma<<<dim3(8, 64, 3), 512, SMEM_CONV_BYTES>>>(bq, bk, bv);

    k_s_mma<<<dim3(8, 8, 64), 512, SMEM_S_BYTES>>>();
    k_stats<<<dim3(128, 64), 256>>>();
    k_av_mma<<<dim3(8, 64), 512, SMEM_AV_BYTES>>>();
    k_proj<<<64, 256>>>(bu, out);
}

// round 17
// speedup vs baseline: 1.0756x; 1.0756x over previous
#include <cuda_runtime.h>
#include <cuda_fp16.h>
#include <math.h>
#include <stdint.h>

// ---------------------------------------------------------------------------
// SelfAttentionConv: B=8, T=1024, K=128, H=8, TOP_K=64, KS=5
// Round 17: R15 build restored (s_mma 128x64, 256thr); k_proj converted to
// fp16x3 HMMA (O stored as fp16 hi/lo planes by k_av; Wu pre-split fp16).
// ---------------------------------------------------------------------------

#define SCALE_QK 0.2973017787506803f   // 128^-0.25

__device__ float g_S    [67108864];        // 64 * 1024 * 1024 fp32 scores
__device__ float g_stats[65536 * 4];       // per-row: thresh, rmin, off, pad
// fp16 hi/lo operand planes
__device__ __align__(128) __half g_xh  [1052672];   // [b][1028][128], 4 pad rows
__device__ __align__(128) __half g_xl  [1052672];
__device__ __align__(128) __half g_WqTh[655360];    // [cg][640] K-major
__device__ __align__(128) __half g_WqTl[655360];
__device__ __align__(128) __half g_WkTh[655360];
__device__ __align__(128) __half g_WkTl[655360];
__device__ __align__(128) __half g_WvTh[131072];    // [cg][128]
__device__ __align__(128) __half g_WvTl[131072];
__device__ __align__(128) __half g_WuTh[131072];    // [c][k=1024] (native Wu)
__device__ __align__(128) __half g_WuTl[131072];
__device__ __align__(128) __half g_Qh[8388608];     // [g][ki] fp16 hi
__device__ __align__(128) __half g_Ql[8388608];
__device__ __align__(128) __half g_Kh[8388608];
__device__ __align__(128) __half g_Kl[8388608];
__device__ __align__(128) __half g_Vth[8388608];    // [bh][ki][s] fp16 hi
__device__ __align__(128) __half g_Vtl[8388608];    // fp16 lo
__device__ __align__(128) __half g_Oh [8388608];    // [g2][ki] fp16 hi
__device__ __align__(128) __half g_Ol [8388608];    // fp16 lo

// ======================= mma.sync helpers ====================================
__device__ __forceinline__ uint32_t smem_u32(const void* p) {
    uint32_t a;
    asm("{ .reg .u64 t; cvta.to.shared.u64 t, %1; cvt.u32.u64 %0, t; }"
        : "=r"(a) : "l"(p));
    return a;
}
__device__ __forceinline__ void cpa16(uint32_t dst, const void* src) {
    asm volatile("cp.async.cg.shared.global [%0], [%1], 16;"
                 :: "r"(dst), "l"(src));
}
#define CPA_COMMIT() asm volatile("cp.async.commit_group;" ::: "memory")
#define CPA_WAIT(n)  asm volatile("cp.async.wait_group %0;" :: "n"(n) : "memory")

#define LDSM4(R, addr)                                                        \
    asm volatile("ldmatrix.sync.aligned.m8n8.x4.shared.b16 "                  \
                 "{%0, %1, %2, %3}, [%4];"                                    \
                 : "=r"((R)[0]), "=r"((R)[1]), "=r"((R)[2]), "=r"((R)[3])     \
                 : "r"(addr))

__device__ __forceinline__ void mma_f16(float* d, const unsigned* a,
                                        const unsigned* b) {
    asm volatile(
        "mma.sync.aligned.m16n8k16.row.col.f32.f16.f16.f32 "
        "{%0, %1, %2, %3}, {%4, %5, %6, %7}, {%8, %9}, {%0, %1, %2, %3};"
        : "+f"(d[0]), "+f"(d[1]), "+f"(d[2]), "+f"(d[3])
        : "r"(a[0]), "r"(a[1]), "r"(a[2]), "r"(a[3]), "r"(b[0]), "r"(b[1]));
}

// ---- k_s_mma smem layout (128x64 tile, R15) ----------------------------------
#define SQ_AH 0
#define SQ_AL 34816
#define SQ_BH 69632
#define SQ_BL 87040
#define SMEM_S_BYTES 104448

// ---- conv smem ----------------------------------------------------------------
#define CV_AH 0
#define CV_AL 35904
#define CV_B  71808
#define SMEM_CONV_BYTES 211072

// ---- k_av smem: P fp16 plane + V fp16 hi/lo + fp32 S stage + stats ----------
#define TSTRIDE 272
#define S_AH  0
#define S_BH  34816
#define S_BL  69632
#define S_STG 104448
#define S_ST  169984
#define SMEM_AV_BYTES 172032

// ---- k_proj smem: A hi/lo + B hi/lo (128x128 fp16 each) ----------------------
#define PJ_AH 0
#define PJ_AL 34816
#define PJ_BH 69632
#define PJ_BL 104448
#define SMEM_PJ_BYTES 139264

// order-preserving float<->key bijection
__device__ __forceinline__ unsigned f2k(unsigned u) {
    return (u & 0x80000000u) ? ~u : (u | 0x80000000u);
}
__device__ __forceinline__ float k2f(unsigned k) {
    unsigned u = (k & 0x80000000u) ? (k & 0x7FFFFFFFu) : ~k;
    return __uint_as_float(u);
}

// ---------------- merged prep: pad/split x, split weights --------------------
#define PX_X  1052672
#define PX_WQ 1708032
#define PX_WK 2363392
#define PX_WV 2494464
#define PX_WU 2625536
__global__ void k_prep(const float* __restrict__ x,
                       const float* __restrict__ Wq, const float* __restrict__ Wk,
                       const float* __restrict__ Wv, const float* __restrict__ Wu) {
    int idx = blockIdx.x * 256 + threadIdx.x;
    if (idx < PX_X) {
        int b = idx / 131584, rem = idx % 131584;
        int row = rem >> 7, ci = rem & 127;
        int t = row - 4;
        float v = (t >= 0) ? x[(((b << 10) | t) << 7) + ci] : 0.f;
        __half h = __float2half_rn(v);
        g_xh[idx] = h;
        g_xl[idx] = __float2half_rn(v - __half2float(h));
    } else if (idx < PX_WQ) {
        int i = idx - PX_X;
        int cg = i / 640, k = i % 640, j = k >> 7, ci = k & 127;
        float v = Wq[(cg * 128 + ci) * 5 + j];
        __half h = __float2half_rn(v);
        g_WqTh[i] = h;
        g_WqTl[i] = __float2half_rn(v - __half2float(h));
    } else if (idx < PX_WK) {
        int i = idx - PX_WQ;
        int cg = i / 640, k = i % 640, j = k >> 7, ci = k & 127;
        float v = Wk[(cg * 128 + ci) * 5 + j];
        __half h = __float2half_rn(v);
        g_WkTh[i] = h;
        g_WkTl[i] = __float2half_rn(v - __half2float(h));
    } else if (idx < PX_WV) {
        int i = idx - PX_WK;
        float v = Wv[i];
        __half h = __float2half_rn(v);
        g_WvTh[i] = h;
        g_WvTl[i] = __float2half_rn(v - __half2float(h));
    } else if (idx < PX_WU) {
        int i = idx - PX_WV;
        float v = Wu[i];                    // native [c][k] layout
        __half h = __float2half_rn(v);
        g_WuTh[i] = h;
        g_WuTl[i] = __float2half_rn(v - __half2float(h));
    }
}

// ---------------- pipelined conv via fp16x3 HMMA -----------------------------
__global__ __launch_bounds__(512, 1) void k_conv_mma(
    const float* __restrict__ bq, const float* __restrict__ bk,
    const float* __restrict__ bv)
{
    extern __shared__ char sm[];
    const uint32_t smb = smem_u32(sm);
    const int tid = threadIdx.x, lane = tid & 31, wid = tid >> 5;
    const int rowBase = blockIdx.y * 128;
    const int colBase = blockIdx.x * 128;
    const int z = blockIdx.z;
    const int b = rowBase >> 10, t0 = rowBase & 1023;
    const int wm = wid >> 2, wn = wid & 3;

    const __half* Wth = (z == 0) ? g_WqTh : (z == 1) ? g_WkTh : g_WvTh;
    const __half* Wtl = (z == 0) ? g_WqTl : (z == 1) ? g_WkTl : g_WvTl;
    const float* bias = (z == 0) ? bq : (z == 1) ? bk : bv;
    const float scale = (z == 2) ? 1.0f : SCALE_QK;
    const int nJ   = (z == 2) ? 1 : 5;
    const int tAdd = (z == 2) ? 4 : 0;
    const int Wstride = nJ * 128;

    {
        const size_t base = (size_t)(b * 1028 + t0) * 128;
#pragma unroll
        for (int i = 0; i < 5; i++) {
            int c = i * 512 + tid;
            if (c < 132 * 16) {
                int r = c >> 4, q = c & 15;
                uint32_t d = smb + CV_AH + r * 272 + q * 16;
                cpa16(d,         g_xh + base + (size_t)r * 128 + q * 8);
                cpa16(d + 35904, g_xl + base + (size_t)r * 128 + q * 8);
            }
        }
    }
#pragma unroll
    for (int i = 0; i < 4; i++) {
        int c = i * 512 + tid;
        int r = c >> 4, q = c & 15;
        uint32_t d = smb + CV_B + r * 272 + q * 16;
        size_t so = (size_t)(colBase + r) * Wstride + q * 8;
        cpa16(d,         Wth + so);
        cpa16(d + 34816, Wtl + so);
    }
    CPA_COMMIT();

    float acc[2][4][4];
#pragma unroll
    for (int i = 0; i < 2; i++)
#pragma unroll
        for (int j = 0; j < 4; j++)
#pragma unroll
            for (int e = 0; e < 4; e++) acc[i][j][e] = 0.f;

    const int aRow = wm * 32 + (lane & 7) + ((lane >> 3) & 1) * 8;
    const int aKb  = (lane >> 4) * 16;
    const int bRow = wn * 32 + ((lane >> 4) & 1) * 8 + (lane & 7);
    const int bKb  = ((lane >> 3) & 1) * 16;

    int buf = 0;
    for (int j = 0; j < nJ; j++) {
        CPA_WAIT(0);
        __syncthreads();

        if (j + 1 < nJ) {
#pragma unroll
            for (int i = 0; i < 4; i++) {
                int c = i * 512 + tid;
                int r = c >> 4, q = c & 15;
                uint32_t d = smb + CV_B + (buf ^ 1) * 69632 + r * 272 + q * 16;
                size_t so = (size_t)(colBase + r) * Wstride + (j + 1) * 128 + q * 8;
                cpa16(d,         Wth + so);
                cpa16(d + 34816, Wtl + so);
            }
            CPA_COMMIT();
        }

        const uint32_t aHj = smb + CV_AH + (aRow + j + tAdd) * 272 + aKb;
        const uint32_t aLj = aHj + 35904;
        const uint32_t bHj = smb + CV_B + buf * 69632 + bRow * 272 + bKb;
        const uint32_t bLj = bHj + 34816;

#pragma unroll
        for (int k = 0; k < 8; k++) {
            const int kb = k * 32;
            unsigned ah[2][4], al[2][4], bhr[4][2], blr[4][2];
#pragma unroll
            for (int mf = 0; mf < 2; mf++) {
                LDSM4(ah[mf], aHj + mf * 16 * 272 + kb);
                LDSM4(al[mf], aLj + mf * 16 * 272 + kb);
            }
#pragma unroll
            for (int g2 = 0; g2 < 2; g2++) {
                LDSM4(&bhr[2 * g2][0], bHj + g2 * 16 * 272 + kb);
                LDSM4(&blr[2 * g2][0], bLj + g2 * 16 * 272 + kb);
            }
#pragma unroll
            for (int mf = 0; mf < 2; mf++)
#pragma unroll
                for (int nf = 0; nf < 4; nf++) {
                    mma_f16(acc[mf][nf], ah[mf], bhr[nf]);
                    mma_f16(acc[mf][nf], ah[mf], blr[nf]);
                    mma_f16(acc[mf][nf], al[mf], bhr[nf]);
                }
        }
        buf ^= 1;
    }

    const int r0 = rowBase + wm * 32 + (lane >> 2);
    const int c0 = colBase + wn * 32 + (lane & 3) * 2;
#pragma unroll
    for (int mf = 0; mf < 2; mf++)
#pragma unroll
        for (int nf = 0; nf < 4; nf++)
#pragma unroll
            for (int e = 0; e < 4; e++) {
                int m  = r0 + mf * 16 + (e >> 1) * 8;
                int cg = c0 + nf * 8 + (e & 1);
                float val = (acc[mf][nf][e] + bias[cg]) * scale;
                int b2 = m >> 10, t2 = m & 1023;
                int hh = cg & 7, ki = cg >> 3;
                int g = (b2 << 13) | (t2 << 3) | hh;
                __half h = __float2half_rn(val);
                __half l = __float2half_rn(val - __half2float(h));
                if (z == 0) {
                    g_Qh[(size_t)g * 128 + ki] = h;
                    g_Ql[(size_t)g * 128 + ki] = l;
                } else if (z == 1) {
                    g_Kh[(size_t)g * 128 + ki] = h;
                    g_Kl[(size_t)g * 128 + ki] = l;
                } else {
                    size_t idx = (size_t)((g >> 10) * 128 + ki) * 1024 + (g & 1023);
                    g_Vth[idx] = h;
                    g_Vtl[idx] = l;
                }
            }
}

// ---------------- S = Q K^T via mma.sync fp16x3 (R15: 128x64, 256thr) --------
__global__ __launch_bounds__(256, 2) void k_s_mma() {
    extern __shared__ char sm[];
    const uint32_t smb = smem_u32(sm);
    const int tid = threadIdx.x, lane = tid & 31, wid = tid >> 5;
    const int nt = blockIdx.x, mt = blockIdx.y, bh = blockIdx.z;

    const __half* Ah = g_Qh + ((size_t)((bh << 10) + mt * 128)) * 128;
    const __half* Al = g_Ql + ((size_t)((bh << 10) + mt * 128)) * 128;
    const __half* Bh = g_Kh + ((size_t)((bh << 10) + nt * 64)) * 128;
    const __half* Bl = g_Kl + ((size_t)((bh << 10) + nt * 64)) * 128;

#pragma unroll
    for (int i = 0; i < 8; i++) {
        int c = i * 256 + tid;
        int r = c >> 4, j = c & 15;
        uint32_t d = smb + SQ_AH + r * 272 + j * 16;
        cpa16(d,         (const char*)Ah + r * 256 + j * 16);
        cpa16(d + 34816, (const char*)Al + r * 256 + j * 16);
    }
#pragma unroll
    for (int i = 0; i < 4; i++) {
        int c = i * 256 + tid;
        int r = c >> 4, j = c & 15;
        uint32_t d = smb + SQ_BH + r * 272 + j * 16;
        cpa16(d,         (const char*)Bh + r * 256 + j * 16);
        cpa16(d + 17408, (const char*)Bl + r * 256 + j * 16);
    }
    CPA_COMMIT();
    CPA_WAIT(0);
    __syncthreads();

    const int wm = wid >> 1, wn = wid & 1;
    float acc[2][4][4];
#pragma unroll
    for (int i = 0; i < 2; i++)
#pragma unroll
        for (int j = 0; j < 4; j++)
#pragma unroll
            for (int e = 0; e < 4; e++) acc[i][j][e] = 0.f;

    const int aRow = wm * 32 + (lane & 7) + ((lane >> 3) & 1) * 8;
    const int aKb  = (lane >> 4) * 16;
    const int bRow = wn * 32 + ((lane >> 4) & 1) * 8 + (lane & 7);
    const int bKb  = ((lane >> 3) & 1) * 16;
    const uint32_t aH = smb + SQ_AH + aRow * 272 + aKb;
    const uint32_t aL = smb + SQ_AL + aRow * 272 + aKb;
    const uint32_t bH = smb + SQ_BH + bRow * 272 + bKb;
    const uint32_t bL = smb + SQ_BL + bRow * 272 + bKb;

#pragma unroll
    for (int k = 0; k < 8; k++) {
        const int kb = k * 32;
        unsigned ah[2][4], al[2][4], bhr[4][2], blr[4][2];
#pragma unroll
        for (int mf = 0; mf < 2; mf++) {
            LDSM4(ah[mf], aH + mf * 16 * 272 + kb);
            LDSM4(al[mf], aL + mf * 16 * 272 + kb);
        }
#pragma unroll
        for (int g2 = 0; g2 < 2; g2++) {
            LDSM4(&bhr[2 * g2][0], bH + g2 * 16 * 272 + kb);
            LDSM4(&blr[2 * g2][0], bL + g2 * 16 * 272 + kb);
        }
#pragma unroll
        for (int mf = 0; mf < 2; mf++)
#pragma unroll
            for (int nf = 0; nf < 4; nf++) {
                mma_f16(acc[mf][nf], ah[mf], bhr[nf]);
                mma_f16(acc[mf][nf], ah[mf], blr[nf]);
                mma_f16(acc[mf][nf], al[mf], bhr[nf]);
            }
    }

    float* C = g_S + ((size_t)bh << 20);
    const int r0 = mt * 128 + wm * 32 + (lane >> 2);
    const int c0 = nt * 64 + wn * 32 + (lane & 3) * 2;
#pragma unroll
    for (int mf = 0; mf < 2; mf++)
#pragma unroll
        for (int nf = 0; nf < 4; nf++) {
            int rr = r0 + mf * 16, cc = c0 + nf * 8;
            *(float2*)&C[(size_t)rr * 1024 + cc] =
                make_float2(acc[mf][nf][0], acc[mf][nf][1]);
            *(float2*)&C[(size_t)(rr + 8) * 1024 + cc] =
                make_float2(acc[mf][nf][2], acc[mf][nf][3]);
        }
}

// ---------------- per-row stats: R14 radix, key-resident registers -----------
__global__ __launch_bounds__(256) void k_stats() {
    __shared__ unsigned hist[8][256];
    const int tid = threadIdx.x, lane = tid & 31, wid = tid >> 5;
    const int t  = blockIdx.x * 8 + wid;
    const int bh = blockIdx.y;
    const float* row = g_S + ((size_t)bh << 20) + ((size_t)t << 10);

    unsigned keys[32];
#pragma unroll
    for (int i = 0; i < 8; i++) {
        uint4 v = ((const uint4*)row)[lane + i * 32];
        keys[i * 4 + 0] = f2k(v.x);
        keys[i * 4 + 1] = f2k(v.y);
        keys[i * 4 + 2] = f2k(v.z);
        keys[i * 4 + 3] = f2k(v.w);
    }

    unsigned kmin = keys[0];
#pragma unroll
    for (int i = 1; i < 32; i++) kmin = min(kmin, keys[i]);
#pragma unroll
    for (int off = 16; off; off >>= 1)
        kmin = min(kmin, __shfl_xor_sync(0xffffffffu, kmin, off));

    unsigned prefix = 0u, need = 64u;
#pragma unroll
    for (int pass = 0; pass < 4; pass++) {
        const int shift = 24 - pass * 8;
        const unsigned mask = (pass == 0) ? 0u : (0xFFFFFFFFu << (shift + 8));
#pragma unroll
        for (int j = 0; j < 8; j++) hist[wid][lane * 8 + j] = 0u;
        __syncwarp();
#pragma unroll
        for (int i = 0; i < 32; i++) {
            if ((keys[i] & mask) == prefix)
                atomicAdd(&hist[wid][(keys[i] >> shift) & 255u], 1u);
        }
        __syncwarp();
        unsigned h8[8], suf[8], run = 0u;
#pragma unroll
        for (int j = 7; j >= 0; j--) {
            h8[j] = hist[wid][lane * 8 + j];
            run += h8[j];
            suf[j] = run;
        }
        unsigned s = run;
#pragma unroll
        for (int off = 1; off < 32; off <<= 1) {
            unsigned v = __shfl_down_sync(0xffffffffu, s, off);
            if (lane + off < 32) s += v;
        }
        unsigned tail = s - run;
        int sel = -1; unsigned nneed = 0u;
#pragma unroll
        for (int j = 0; j < 8; j++) {
            unsigned cum  = suf[j] + tail;
            unsigned cumN = cum - h8[j];
            if (cum >= need && cumN < need) { sel = lane * 8 + j; nneed = need - cumN; }
        }
        unsigned bal = __ballot_sync(0xffffffffu, sel >= 0);
        int src = __ffs(bal) - 1;
        sel   = __shfl_sync(0xffffffffu, sel, src);
        nneed = __shfl_sync(0xffffffffu, nneed, src);
        prefix |= ((unsigned)sel << shift);
        need = nneed;
        __syncwarp();
    }
    const unsigned tkey = prefix;
    const float thresh = k2f(tkey);

    float mx = -1e30f;
    float fv[32];
#pragma unroll
    for (int i = 0; i < 32; i++) {
        int s_ = 4 * (lane + (i >> 2) * 32) + (i & 3);
        unsigned pk = (keys[i] >= tkey) ? keys[i] : kmin;
        float pv = k2f(pk);
        fv[i] = pv;
        if (s_ <= t) mx = fmaxf(mx, pv);
    }
#pragma unroll
    for (int off = 16; off; off >>= 1)
        mx = fmaxf(mx, __shfl_xor_sync(0xffffffffu, mx, off));
    float lsum = 0.f;
#pragma unroll
    for (int i = 0; i < 32; i++) {
        int s_ = 4 * (lane + (i >> 2) * 32) + (i & 3);
        if (s_ <= t) lsum += __expf(fv[i] - mx);
    }
#pragma unroll
    for (int off = 16; off; off >>= 1)
        lsum += __shfl_xor_sync(0xffffffffu, lsum, off);
    if (lane == 0) {
        float off0 = mx + __logf(lsum);
        ((float4*)g_stats)[(bh << 10) + t] =
            make_float4(thresh, k2f(kmin), off0, 0.f);
    }
}

// ---------------- O = P V via mma.sync fp16x2 (staged causal pipeline) -------
__global__ __launch_bounds__(512, 1) void k_av_mma() {
    extern __shared__ char sm[];
    const int tid = threadIdx.x, lane = tid & 31, wid = tid >> 5;
    const int mt = gridDim.x - 1 - blockIdx.x;   // longest CTAs first
    const int bh = blockIdx.y;
    const int rowBase = mt * 128;
    const uint32_t smb = smem_u32(sm);
    const int wm = wid >> 2, wn = wid & 3;

    if (tid < 128)
        ((float4*)(sm + S_ST))[tid] =
            ((const float4*)g_stats)[(bh << 10) + rowBase + tid];

#pragma unroll
    for (int it = 0; it < 8; it++) {
        int idx = it * 512 + tid;
        int r = idx >> 5, j = idx & 31;
        cpa16(smb + S_STG + r * 512 + j * 16,
              &g_S[((size_t)bh << 20) + (size_t)(rowBase + r) * 1024 + j * 4]);
    }
    CPA_COMMIT();

    float acc[2][4][4];
#pragma unroll
    for (int i = 0; i < 2; i++)
#pragma unroll
        for (int j = 0; j < 4; j++)
#pragma unroll
            for (int e = 0; e < 4; e++) acc[i][j][e] = 0.f;

    const int aRow = wm * 32 + (lane & 7) + ((lane >> 3) & 1) * 8;
    const int aKb  = (lane >> 4) * 16;
    const int bRow = wn * 32 + ((lane >> 4) & 1) * 8 + (lane & 7);
    const int bKb  = ((lane >> 3) & 1) * 16;
    const uint32_t pH = smb + S_AH + aRow * TSTRIDE + aKb;
    const uint32_t vH = smb + S_BH + bRow * TSTRIDE + bKb;
    const uint32_t vL = smb + S_BL + bRow * TSTRIDE + bKb;

    const int nChunks = mt + 1;
    for (int c = 0; c < nChunks; c++) {
        const int kt = c * 128;
        CPA_WAIT(0);
        __syncthreads();

#pragma unroll
        for (int it = 0; it < 4; it++) {
            int idx = it * 512 + tid;
            int r = idx >> 4, j = idx & 15;
            uint32_t d = smb + S_BH + r * TSTRIDE + j * 16;
            cpa16(d, (const char*)(g_Vth + (size_t)(bh * 128 + r) * 1024 + kt) + j * 16);
            cpa16(d + 34816,
                  (const char*)(g_Vtl + (size_t)(bh * 128 + r) * 1024 + kt) + j * 16);
        }
        CPA_COMMIT();

        // transform staged S chunk -> P (threshold + causal + exp) fp16 plane
#pragma unroll
        for (int i = 0; i < 8; i++) {
            int idx4 = i * 512 + tid;
            int r = idx4 >> 5;
            int s4 = (idx4 & 31) * 4;
            float4 st = ((const float4*)(sm + S_ST))[r];
            const float th = st.x, rm = st.y, off0 = st.z;
            const int tg = rowBase + r;
            float4 v = *(const float4*)(sm + S_STG + r * 512 + s4 * 4);
            float pv[4] = { v.x, v.y, v.z, v.w };
            __half hb[4];
#pragma unroll
            for (int j = 0; j < 4; j++) {
                int sg = kt + s4 + j;
                float p = (pv[j] >= th) ? pv[j] : rm;
                p = (sg <= tg) ? __expf(p - off0) : 0.f;
                hb[j] = __float2half_rn(p);
            }
            __half2 h01 = __halves2half2(hb[0], hb[1]);
            __half2 h23 = __halves2half2(hb[2], hb[3]);
            int off = r * TSTRIDE + s4 * 2;
            *(uint2*)(sm + S_AH + off) =
                make_uint2(*(unsigned*)&h01, *(unsigned*)&h23);
        }
        __syncthreads();

        if (c + 1 < nChunks) {
            const int kt2 = kt + 128;
#pragma unroll
            for (int it = 0; it < 8; it++) {
                int idx = it * 512 + tid;
                int r = idx >> 5, j = idx & 31;
                cpa16(smb + S_STG + r * 512 + j * 16,
                      &g_S[((size_t)bh << 20) + (size_t)(rowBase + r) * 1024
                           + kt2 + j * 4]);
            }
            CPA_COMMIT();
            CPA_WAIT(1);
        } else {
            CPA_WAIT(0);
        }
        __syncthreads();

#pragma unroll
        for (int k = 0; k < 8; k++) {
            const int kb = k * 32;
            unsigned ah[2][4], bhr[4][2], blr[4][2];
#pragma unroll
            for (int mf = 0; mf < 2; mf++)
                LDSM4(ah[mf], pH + mf * 16 * TSTRIDE + kb);
#pragma unroll
            for (int g2 = 0; g2 < 2; g2++) {
                LDSM4(&bhr[2 * g2][0], vH + g2 * 16 * TSTRIDE + kb);
                LDSM4(&blr[2 * g2][0], vL + g2 * 16 * TSTRIDE + kb);
            }
#pragma unroll
            for (int mf = 0; mf < 2; mf++)
#pragma unroll
                for (int nf = 0; nf < 4; nf++) {
                    mma_f16(acc[mf][nf], ah[mf], bhr[nf]);
                    mma_f16(acc[mf][nf], ah[mf], blr[nf]);
                }
        }
    }

    // epilogue -> g_Oh / g_Ol (fp16 hi/lo planes)
    const int r0 = (bh << 10) + rowBase + wm * 32 + (lane >> 2);
    const int c0 = wn * 32 + (lane & 3) * 2;
#pragma unroll
    for (int mf = 0; mf < 2; mf++)
#pragma unroll
        for (int nf = 0; nf < 4; nf++) {
            int rr = r0 + mf * 16, cc = c0 + nf * 8;
            float v0 = acc[mf][nf][0], v1 = acc[mf][nf][1];
            float v2 = acc[mf][nf][2], v3 = acc[mf][nf][3];
            __half h0 = __float2half_rn(v0), h1 = __float2half_rn(v1);
            __half h2 = __float2half_rn(v2), h3 = __float2half_rn(v3);
            __half l0 = __float2half_rn(v0 - __half2float(h0));
            __half l1 = __float2half_rn(v1 - __half2float(h1));
            __half l2 = __float2half_rn(v2 - __half2float(h2));
            __half l3 = __float2half_rn(v3 - __half2float(h3));
            __half2 hh01 = __halves2half2(h0, h1), ll01 = __halves2half2(l0, l1);
            __half2 hh23 = __halves2half2(h2, h3), ll23 = __halves2half2(l2, l3);
            *(unsigned*)&g_Oh[(size_t)rr * 128 + cc] = *(unsigned*)&hh01;
            *(unsigned*)&g_Ol[(size_t)rr * 128 + cc] = *(unsigned*)&ll01;
            *(unsigned*)&g_Oh[(size_t)(rr + 8) * 128 + cc] = *(unsigned*)&hh23;
            *(unsigned*)&g_Ol[(size_t)(rr + 8) * 128 + cc] = *(unsigned*)&ll23;
        }
}

// ---------------- final projection via fp16x3 HMMA ---------------------------
// out[m][c] = sum_{hf,ki} O[(b,hf,tf)][ki] * Wu[c][hf*128+ki] + bu[c]
__global__ __launch_bounds__(512, 1) void k_proj_mma(
    const float* __restrict__ bu, float* __restrict__ out)
{
    extern __shared__ char sm[];
    const uint32_t smb = smem_u32(sm);
    const int tid = threadIdx.x, lane = tid & 31, wid = tid >> 5;
    const int rowBase = blockIdx.x * 128;
    const int b = rowBase >> 10, t0 = rowBase & 1023;
    const int wm = wid >> 2, wn = wid & 3;

    float acc[2][4][4];
#pragma unroll
    for (int i = 0; i < 2; i++)
#pragma unroll
        for (int j = 0; j < 4; j++)
#pragma unroll
            for (int e = 0; e < 4; e++) acc[i][j][e] = 0.f;

    const int aRow = wm * 32 + (lane & 7) + ((lane >> 3) & 1) * 8;
    const int aKb  = (lane >> 4) * 16;
    const int bRow = wn * 32 + ((lane >> 4) & 1) * 8 + (lane & 7);
    const int bKb  = ((lane >> 3) & 1) * 16;
    const uint32_t aH = smb + PJ_AH + aRow * 272 + aKb;
    const uint32_t aL = smb + PJ_AL + aRow * 272 + aKb;
    const uint32_t bH = smb + PJ_BH + bRow * 272 + bKb;
    const uint32_t bL = smb + PJ_BL + bRow * 272 + bKb;

    for (int hf = 0; hf < 8; hf++) {
        // A: O rows ((b<<13)+(hf<<10)+t0 .. +127), 128 cols fp16 hi/lo
        const size_t abase = (size_t)((b << 13) + (hf << 10) + t0) * 128;
#pragma unroll
        for (int i = 0; i < 4; i++) {
            int c = i * 512 + tid;
            int r = c >> 4, j = c & 15;
            uint32_t d = smb + r * 272 + j * 16;
            cpa16(d + PJ_AH, g_Oh + abase + (size_t)r * 128 + j * 8);
            cpa16(d + PJ_AL, g_Ol + abase + (size_t)r * 128 + j * 8);
            cpa16(d + PJ_BH, g_WuTh + (size_t)r * 1024 + hf * 128 + j * 8);
            cpa16(d + PJ_BL, g_WuTl + (size_t)r * 1024 + hf * 128 + j * 8);
        }
        CPA_COMMIT();
        CPA_WAIT(0);
        __syncthreads();

#pragma unroll
        for (int k = 0; k < 8; k++) {
            const int kb = k * 32;
            unsigned ah[2][4], al[2][4], bhr[4][2], blr[4][2];
#pragma unroll
            for (int mf = 0; mf < 2; mf++) {
                LDSM4(ah[mf], aH + mf * 16 * 272 + kb);
                LDSM4(al[mf], aL + mf * 16 * 272 + kb);
            }
#pragma unroll
            for (int g2 = 0; g2 < 2; g2++) {
                LDSM4(&bhr[2 * g2][0], bH + g2 * 16 * 272 + kb);
                LDSM4(&blr[2 * g2][0], bL + g2 * 16 * 272 + kb);
            }
#pragma unroll
            for (int mf = 0; mf < 2; mf++)
#pragma unroll
                for (int nf = 0; nf < 4; nf++) {
                    mma_f16(acc[mf][nf], ah[mf], bhr[nf]);
                    mma_f16(acc[mf][nf], ah[mf], blr[nf]);
                    mma_f16(acc[mf][nf], al[mf], bhr[nf]);
                }
        }
        __syncthreads();   // tile consumed before next hf overwrites
    }

    const int r0 = rowBase + wm * 32 + (lane >> 2);
    const int c0 = wn * 32 + (lane & 3) * 2;
#pragma unroll
    for (int mf = 0; mf < 2; mf++)
#pragma unroll
        for (int nf = 0; nf < 4; nf++) {
            int rr = r0 + mf * 16, cc = c0 + nf * 8;
            *(float2*)&out[(size_t)rr * 128 + cc] =
                make_float2(acc[mf][nf][0] + bu[cc],
                            acc[mf][nf][1] + bu[cc + 1]);
            *(float2*)&out[(size_t)(rr + 8) * 128 + cc] =
                make_float2(acc[mf][nf][2] + bu[cc],
                            acc[mf][nf][3] + bu[cc + 1]);
        }
}

// ---------------------------------------------------------------------------
extern "C" void kernel_launch(void* const* d_in, const int* in_sizes, int n_in,
                              void* d_out, int out_size) {
    const float* x  = (const float*)d_in[0];
    const float* Wq = (const float*)d_in[1];
    const float* bq = (const float*)d_in[2];
    const float* Wk = (const float*)d_in[3];
    const float* bk = (const float*)d_in[4];
    const float* Wv = (const float*)d_in[5];
    const float* bv = (const float*)d_in[6];
    const float* Wu = (const float*)d_in[7];
    const float* bu = (const float*)d_in[8];
    float* out = (float*)d_out;

    cudaFuncSetAttribute(k_conv_mma,
        cudaFuncAttributeMaxDynamicSharedMemorySize, SMEM_CONV_BYTES);
    cudaFuncSetAttribute(k_s_mma,
        cudaFuncAttributeMaxDynamicSharedMemorySize, SMEM_S_BYTES);
    cudaFuncSetAttribute(k_av_mma,
        cudaFuncAttributeMaxDynamicSharedMemorySize, SMEM_AV_BYTES);
    cudaFuncSetAttribute(k_proj_mma,
        cudaFuncAttributeMaxDynamicSharedMemorySize, SMEM_PJ_BYTES);

    k_prep<<<10256, 256>>>(x, Wq, Wk, Wv, Wu);

    k_conv_mma<<<dim3(8, 64, 3), 512, SMEM_CONV_BYTES>>>(bq, bk, bv);

    k_s_mma<<<dim3(16, 8, 64), 256, SMEM_S_BYTES>>>();
    k_stats<<<dim3(128, 64), 256>>>();
    k_av_mma<<<dim3(8, 64), 512, SMEM_AV_BYTES>>>();
    k_proj_mma<<<64, 512, SMEM_PJ_BYTES>>>(bu, out);
}